// round 12
// baseline (speedup 1.0000x reference)
#include <cuda_runtime.h>
#include <math.h>

// Fixed problem shapes
constexpr int B  = 8;
constexpr int H  = 384;
constexpr int W  = 512;
constexpr int HW = H * W;            // 196608
constexpr int NPIX = B * HW;         // 1572864
constexpr int N2 = B * 2 * HW;

constexpr int TPB = 256;
constexpr int NQUAD = NPIX / 4;
constexpr int NBLKQ = NQUAD / TPB;   // 1536

// Fused-tile geometry: 64x16 interior, halo 4 in x (float4-aligned), 2 in y
constexpr int TX = 64;
constexpr int TY = 16;
constexpr int SW_ = TX + 8;          // 72
constexpr int SH_ = TY + 4;          // 20

// 5-tap gradient filter coefficients (center tap is 0)
constexpr float KC0 = -1.0f / 12.0f;
constexpr float KC1 =  2.0f / 3.0f;
constexpr float KC3 = -2.0f / 3.0f;
constexpr float KC4 =  1.0f / 12.0f;

// Scratch (static device globals)
__device__ float g_flow[2][N2];      // [0]=flowf, [1]=flowb
__device__ float g_acc [3];          // [0]=energy, [1]=logvar raw sum, [2]=epe sum

__device__ __forceinline__ float sigm(float x) {
    return 1.0f / (1.0f + __expf(-x));
}
__device__ __forceinline__ float4 ld4(const float* p) {
    return *reinterpret_cast<const float4*>(p);
}
__device__ __forceinline__ void st4(float* p, float4 v) {
    *reinterpret_cast<float4*>(p) = v;
}
__device__ __forceinline__ void unpack(float4 v, float* a) {
    a[0] = v.x; a[1] = v.y; a[2] = v.z; a[3] = v.w;
}

struct Bilin { float w00, w10, w01, w11; int i00, i10, i01, i11; };

__device__ __forceinline__ Bilin bilin(float Xp, float Yp) {
    float x0f = floorf(Xp), y0f = floorf(Yp);
    float wx = Xp - x0f,    wy = Yp - y0f;
    int x0 = (int)x0f, y0 = (int)y0f;
    bool vx0 = (x0 >= 0)     && (x0 <= W - 1);
    bool vx1 = (x0 + 1 >= 0) && (x0 + 1 <= W - 1);
    bool vy0 = (y0 >= 0)     && (y0 <= H - 1);
    bool vy1 = (y0 + 1 >= 0) && (y0 + 1 <= H - 1);
    Bilin r;
    r.w00 = (1.0f - wx) * (1.0f - wy) * (float)(vx0 && vy0);
    r.w10 = wx * (1.0f - wy)          * (float)(vx1 && vy0);
    r.w01 = (1.0f - wx) * wy          * (float)(vx0 && vy1);
    r.w11 = wx * wy                    * (float)(vx1 && vy1);
    int cx0 = min(max(x0, 0), W - 1);
    int cx1 = min(max(x0 + 1, 0), W - 1);
    int cy0 = min(max(y0, 0), H - 1);
    int cy1 = min(max(y0 + 1, 0), H - 1);
    r.i00 = cy0 * W + cx0;
    r.i10 = cy0 * W + cx1;
    r.i01 = cy1 * W + cx0;
    r.i11 = cy1 * W + cx1;
    return r;
}

__device__ __forceinline__ float blockReduceSum(float v) {
    __shared__ float s[32];
    int lane = threadIdx.x & 31;
    int wid  = threadIdx.x >> 5;
    #pragma unroll
    for (int o = 16; o; o >>= 1) v += __shfl_down_sync(0xffffffffu, v, o);
    if (lane == 0) s[wid] = v;
    __syncthreads();
    v = 0.0f;
    if (wid == 0) {
        v = (lane < (TPB >> 5)) ? s[lane] : 0.0f;
        #pragma unroll
        for (int o = 16; o; o >>= 1) v += __shfl_down_sync(0xffffffffu, v, o);
    }
    return v;
}

__global__ void k_zero() {
    if (threadIdx.x < 3) g_acc[threadIdx.x] = 0.0f;
}

// Reparameterize flows (float4), accumulate entropy raw-sum and EPE sum.
__global__ void __launch_bounds__(TPB) k_flow(
    const float* __restrict__ mf, const float* __restrict__ lvf,
    const float* __restrict__ mb, const float* __restrict__ lvb,
    const float* __restrict__ tgt,
    const float* __restrict__ nf, const float* __restrict__ nb)
{
    int q = blockIdx.x * blockDim.x + threadIdx.x;
    int p = q * 4;
    int b  = p / HW;
    int rr = p - b * HW;
    int i0 = (b * 2) * HW + rr;
    int i1 = i0 + HW;

    float mf0[4], mf1[4], lf0[4], lf1[4], mb0[4], mb1[4], lb0[4], lb1[4];
    float t0[4], t1[4], nf0[4], nf1[4], nb0[4], nb1[4];
    unpack(ld4(mf  + i0), mf0); unpack(ld4(mf  + i1), mf1);
    unpack(ld4(lvf + i0), lf0); unpack(ld4(lvf + i1), lf1);
    unpack(ld4(mb  + i0), mb0); unpack(ld4(mb  + i1), mb1);
    unpack(ld4(lvb + i0), lb0); unpack(ld4(lvb + i1), lb1);
    unpack(ld4(tgt + i0), t0);  unpack(ld4(tgt + i1), t1);
    unpack(ld4(nf  + i0), nf0); unpack(ld4(nf  + i1), nf1);
    unpack(ld4(nb  + i0), nb0); unpack(ld4(nb  + i1), nb1);

    float ff0[4], ff1[4], fb0[4], fb1[4];
    float ent = 0.0f, epe = 0.0f;
    #pragma unroll
    for (int i = 0; i < 4; ++i) {
        ff0[i] = mf0[i] + __expf(lf0[i] * 0.5f) * nf0[i];
        ff1[i] = mf1[i] + __expf(lf1[i] * 0.5f) * nf1[i];
        fb0[i] = mb0[i] + __expf(lb0[i] * 0.5f) * nb0[i];
        fb1[i] = mb1[i] + __expf(lb1[i] * 0.5f) * nb1[i];
        ent += lf0[i] + lf1[i] + lb0[i] + lb1[i];
        float d0 = mf0[i] - t0[i], d1 = mf1[i] - t1[i];
        epe += sqrtf(d0 * d0 + d1 * d1);
    }
    st4(&g_flow[0][i0], make_float4(ff0[0], ff0[1], ff0[2], ff0[3]));
    st4(&g_flow[0][i1], make_float4(ff1[0], ff1[1], ff1[2], ff1[3]));
    st4(&g_flow[1][i0], make_float4(fb0[0], fb0[1], fb0[2], fb0[3]));
    st4(&g_flow[1][i1], make_float4(fb1[0], fb1[1], fb1[2], fb1[3]));

    float es = blockReduceSum(ent);
    __syncthreads();
    float ps = blockReduceSum(epe);
    if (threadIdx.x == 0) {
        atomicAdd(&g_acc[1], es);
        atomicAdd(&g_acc[2], ps);
    }
}

// Fused per-direction energy: mask/data/fb/smooth + in-block 5-tap gradient term.
// Block tile: 64x16 interior pixels; smem residual tile with (4,2) halo.
__global__ void __launch_bounds__(TPB) k_fused(
    const float* __restrict__ img1, const float* __restrict__ img2)
{
    int dir = blockIdx.z & 1;
    int b   = blockIdx.z >> 1;
    const float* __restrict__ imgA = dir ? img2 : img1;
    const float* __restrict__ imgB = dir ? img1 : img2;
    const float* __restrict__ fA = g_flow[dir];
    const float* __restrict__ fB = g_flow[dir ^ 1];

    int x0 = blockIdx.x * TX;
    int y0 = blockIdx.y * TY;

    int baseF0 = (b * 2) * HW;
    int baseF1 = baseF0 + HW;
    int baseI  = (b * 3) * HW;
    const float* fA0 = fA + baseF0;
    const float* fA1 = fA + baseF1;
    const float* fB0 = fB + baseF0;
    const float* fB1 = fB + baseF1;
    const float* ia0 = imgA + baseI;
    const float* ia1 = ia0 + HW;
    const float* ia2 = ia1 + HW;
    const float* ib0 = imgB + baseI;
    const float* ib1 = ib0 + HW;
    const float* ib2 = ib1 + HW;

    __shared__ float sres[3][SH_][SW_];

    int t  = threadIdx.x;
    int qx = t & 15;        // 16 quads across = 64 px
    int qy = t >> 4;        // 16 rows
    int x  = x0 + qx * 4;
    int y  = y0 + qy;
    int rr = y * W + x;

    // ---- Phase 1a: interior quad, full energy + residual into smem ----
    float fax[4], fay[4];
    unpack(ld4(fA0 + rr), fax);
    unpack(ld4(fA1 + rr), fay);
    float ia[3][4];
    unpack(ld4(ia0 + rr), ia[0]);
    unpack(ld4(ia1 + rr), ia[1]);
    unpack(ld4(ia2 + rr), ia[2]);

    float maskv[4], Dv[4], Av[4];
    float rc[3][4];

    #pragma unroll
    for (int i = 0; i < 4; ++i) {
        float Xp = (float)(x + i) + fax[i];
        float Yp = (float)y + fay[i];

        float mx = sigm(Xp + 0.5f) * (1.0f - sigm(Xp - ((float)W - 0.5f)));
        float my = sigm(Yp + 0.5f) * (1.0f - sigm(Yp - ((float)H - 0.5f)));
        float border = mx * my;

        Bilin bw = bilin(Xp, Yp);

        float fbw0 = bw.w00 * fB0[bw.i00] + bw.w10 * fB0[bw.i10] + bw.w01 * fB0[bw.i01] + bw.w11 * fB0[bw.i11];
        float fbw1 = bw.w00 * fB1[bw.i00] + bw.w10 * fB1[bw.i10] + bw.w01 * fB1[bw.i01] + bw.w11 * fB1[bw.i11];

        float mag = fax[i] * fax[i] + fay[i] * fay[i] + fbw0 * fbw0 + fbw1 * fbw1;
        float dfx = fax[i] + fbw0;
        float dfy = fay[i] + fbw1;
        float D   = dfx * dfx + dfy * dfy;
        float occ = 1.0f - sigm(D - (0.01f * mag + 0.5f));
        maskv[i] = border * occ;
        Dv[i] = D;

        float w0 = bw.w00 * ib0[bw.i00] + bw.w10 * ib0[bw.i10] + bw.w01 * ib0[bw.i01] + bw.w11 * ib0[bw.i11];
        float w1 = bw.w00 * ib1[bw.i00] + bw.w10 * ib1[bw.i10] + bw.w01 * ib1[bw.i01] + bw.w11 * ib1[bw.i11];
        float w2 = bw.w00 * ib2[bw.i00] + bw.w10 * ib2[bw.i10] + bw.w01 * ib2[bw.i01] + bw.w11 * ib2[bw.i11];
        rc[0][i] = ia[0][i] - w0;
        rc[1][i] = ia[1][i] - w1;
        rc[2][i] = ia[2][i] - w2;
        Av[i] = rc[0][i] * rc[0][i] + rc[1][i] * rc[1][i] + rc[2][i] * rc[2][i];
    }

    int sx = qx * 4 + 4;    // smem x of first interior pixel
    int sy = qy + 2;
    #pragma unroll
    for (int c = 0; c < 3; ++c)
        st4(&sres[c][sy][sx], make_float4(rc[c][0], rc[c][1], rc[c][2], rc[c][3]));

    // ---- Phase 1b: halo quads (104 of them), residual only ----
    if (t < 104) {
        int sxq, syh;
        if (t < 36)      { syh = t / 18;            sxq = t % 18; }
        else if (t < 72) { int h = t - 36; syh = 18 + h / 18; sxq = h % 18; }
        else             { int h = t - 72; syh = 2 + (h >> 1); sxq = (h & 1) ? 17 : 0; }
        int hx = x0 - 4 + sxq * 4;
        int hy = y0 - 2 + syh;

        float hr[3][4];
        bool rowIn = (hy >= 0) && (hy < H);
        #pragma unroll
        for (int i = 0; i < 4; ++i) {
            int px = hx + i;
            if (rowIn && px >= 0 && px < W) {
                int prr = hy * W + px;
                float fx = fA0[prr], fy = fA1[prr];
                Bilin bw = bilin((float)px + fx, (float)hy + fy);
                hr[0][i] = ia0[prr] - (bw.w00 * ib0[bw.i00] + bw.w10 * ib0[bw.i10] + bw.w01 * ib0[bw.i01] + bw.w11 * ib0[bw.i11]);
                hr[1][i] = ia1[prr] - (bw.w00 * ib1[bw.i00] + bw.w10 * ib1[bw.i10] + bw.w01 * ib1[bw.i01] + bw.w11 * ib1[bw.i11]);
                hr[2][i] = ia2[prr] - (bw.w00 * ib2[bw.i00] + bw.w10 * ib2[bw.i10] + bw.w01 * ib2[bw.i01] + bw.w11 * ib2[bw.i11]);
            } else {
                hr[0][i] = 0.0f; hr[1][i] = 0.0f; hr[2][i] = 0.0f;
            }
        }
        #pragma unroll
        for (int c = 0; c < 3; ++c)
            st4(&sres[c][syh][sxq * 4], make_float4(hr[c][0], hr[c][1], hr[c][2], hr[c][3]));
    }

    // ---- Smoothness neighbor flow (global, cached) ----
    bool hasR = (x + 4) < W;
    float faxn = hasR ? fA0[rr + 4] : 0.0f;
    float fayn = hasR ? fA1[rr + 4] : 0.0f;
    bool hasD = (y + 1) < H;
    float faxd[4] = {0, 0, 0, 0}, fayd[4] = {0, 0, 0, 0};
    if (hasD) {
        unpack(ld4(fA0 + rr + W), faxd);
        unpack(ld4(fA1 + rr + W), fayd);
    }

    float e = 0.0f;
    #pragma unroll
    for (int i = 0; i < 4; ++i) {
        float dx2 = 0.0f;
        if (x + i < W - 1) {
            float nx = (i < 3) ? fax[i + 1] : faxn;
            float ny = (i < 3) ? fay[i + 1] : fayn;
            float d0 = nx - fax[i];
            float d1 = ny - fay[i];
            dx2 = d0 * d0 + d1 * d1;
        }
        float dy2 = 0.0f;
        if (hasD) {
            float d0 = faxd[i] - fax[i];
            float d1 = fayd[i] - fay[i];
            dy2 = d0 * d0 + d1 * d1;
        }
        e += (1.0f - maskv[i])
           + sqrtf(Av[i] + 1e-5f) * maskv[i]
           + sqrtf(dx2 + dy2 + 1e-5f)
           + sqrtf(Dv[i] + 1e-5f) * maskv[i];
    }

    __syncthreads();

    // ---- Phase 2: gradient-constancy stencil on smem residuals ----
    #pragma unroll
    for (int i = 0; i < 4; ++i) {
        int cx = sx + i;
        float Ct = 0.0f;
        #pragma unroll
        for (int c = 0; c < 3; ++c) {
            const float* row = sres[c][sy];
            float gx = KC0 * row[cx - 2] + KC1 * row[cx - 1]
                     + KC3 * row[cx + 1] + KC4 * row[cx + 2];
            float gy = KC0 * sres[c][sy - 2][cx] + KC1 * sres[c][sy - 1][cx]
                     + KC3 * sres[c][sy + 1][cx] + KC4 * sres[c][sy + 2][cx];
            Ct += gx * gx + gy * gy;
        }
        e += sqrtf(Ct + 1e-5f) * maskv[i];
    }

    float bs = blockReduceSum(e);
    if (threadIdx.x == 0) atomicAdd(&g_acc[0], bs);
}

__global__ void k_final(float* __restrict__ out)
{
    float energy  = g_acc[0] * (1.0f / (float)B);
    float entropy = g_acc[1] * (1.0f / (2.0f * (float)B));
    out[0] = energy - entropy;
    out[1] = g_acc[2] * (1.0f / (float)NPIX);
}

extern "C" void kernel_launch(void* const* d_in, const int* in_sizes, int n_in,
                              void* d_out, int out_size)
{
    const float* meanf   = (const float*)d_in[0];
    const float* logvarf = (const float*)d_in[1];
    const float* meanb   = (const float*)d_in[2];
    const float* logvarb = (const float*)d_in[3];
    const float* img1    = (const float*)d_in[4];
    const float* img2    = (const float*)d_in[5];
    const float* target  = (const float*)d_in[6];
    const float* noise_f = (const float*)d_in[7];
    const float* noise_b = (const float*)d_in[8];
    float* out = (float*)d_out;

    dim3 gridF(W / TX, H / TY, 2 * B);   // 8 x 24 x 16 = 3072 blocks

    k_zero<<<1, 32>>>();
    k_flow<<<NBLKQ, TPB>>>(meanf, logvarf, meanb, logvarb, target, noise_f, noise_b);
    k_fused<<<gridF, TPB>>>(img1, img2);
    k_final<<<1, 1>>>(out);
}

// round 13
// speedup vs baseline: 1.1367x; 1.1367x over previous
#include <cuda_runtime.h>
#include <cuda_fp16.h>
#include <math.h>

// Fixed problem shapes
constexpr int B  = 8;
constexpr int H  = 384;
constexpr int W  = 512;
constexpr int HW = H * W;            // 196608
constexpr int NPIX = B * HW;         // 1572864
constexpr int N2 = B * 2 * HW;
constexpr int N3 = B * 3 * HW;

constexpr int TPB = 256;
constexpr int NQUAD = NPIX / 4;
constexpr int NBLKQ = NQUAD / TPB;     // 1536
constexpr unsigned GRAD_BLOCKS = NBLKQ * 2;  // 3072

// 5-tap gradient filter coefficients (center tap is 0)
constexpr float KC0 = -1.0f / 12.0f;
constexpr float KC1 =  2.0f / 3.0f;
constexpr float KC3 = -2.0f / 3.0f;
constexpr float KC4 =  1.0f / 12.0f;

// Scratch (static device globals; zero-initialized at module load)
__device__ float  g_flow[2][N2];       // fp32 flow samples
__device__ __half g_res [2][N3];       // fp16 warp residual per direction
__device__ __half g_mask[2][NPIX];     // fp16 border*occ mask per direction
__device__ float  g_acc [3];           // [0]=energy, [1]=logvar raw sum, [2]=epe sum
__device__ unsigned g_done;            // last-block counter

__device__ __forceinline__ float sigm(float x) {
    return 1.0f / (1.0f + __expf(-x));
}
__device__ __forceinline__ float4 ld4(const float* p) {
    return *reinterpret_cast<const float4*>(p);
}
__device__ __forceinline__ void st4(float* p, float4 v) {
    *reinterpret_cast<float4*>(p) = v;
}
__device__ __forceinline__ void unpack(float4 v, float* a) {
    a[0] = v.x; a[1] = v.y; a[2] = v.z; a[3] = v.w;
}
// 4 halfs <-> 4 floats, single 8B transaction
__device__ __forceinline__ void st_h4(__half* p, const float* a) {
    __half2 h0 = __floats2half2_rn(a[0], a[1]);
    __half2 h1 = __floats2half2_rn(a[2], a[3]);
    uint2 u;
    u.x = *reinterpret_cast<unsigned*>(&h0);
    u.y = *reinterpret_cast<unsigned*>(&h1);
    *reinterpret_cast<uint2*>(p) = u;
}
__device__ __forceinline__ void ld_h4(const __half* p, float* a) {
    uint2 u = *reinterpret_cast<const uint2*>(p);
    __half2 h0 = *reinterpret_cast<__half2*>(&u.x);
    __half2 h1 = *reinterpret_cast<__half2*>(&u.y);
    float2 f0 = __half22float2(h0);
    float2 f1 = __half22float2(h1);
    a[0] = f0.x; a[1] = f0.y; a[2] = f1.x; a[3] = f1.y;
}

__device__ __forceinline__ float blockReduceSum(float v) {
    __shared__ float s[32];
    int lane = threadIdx.x & 31;
    int wid  = threadIdx.x >> 5;
    #pragma unroll
    for (int o = 16; o; o >>= 1) v += __shfl_down_sync(0xffffffffu, v, o);
    if (lane == 0) s[wid] = v;
    __syncthreads();
    v = 0.0f;
    if (wid == 0) {
        v = (lane < (TPB >> 5)) ? s[lane] : 0.0f;
        #pragma unroll
        for (int o = 16; o; o >>= 1) v += __shfl_down_sync(0xffffffffu, v, o);
    }
    return v;
}

// Reparameterize flows (float4), accumulate entropy raw-sum and EPE sum.
__global__ void __launch_bounds__(TPB) k_flow(
    const float* __restrict__ mf, const float* __restrict__ lvf,
    const float* __restrict__ mb, const float* __restrict__ lvb,
    const float* __restrict__ tgt,
    const float* __restrict__ nf, const float* __restrict__ nb)
{
    int q = blockIdx.x * blockDim.x + threadIdx.x;
    int p = q * 4;
    int b  = p / HW;
    int rr = p - b * HW;
    int i0 = (b * 2) * HW + rr;
    int i1 = i0 + HW;

    float mf0[4], mf1[4], lf0[4], lf1[4], mb0[4], mb1[4], lb0[4], lb1[4];
    float t0[4], t1[4], nf0[4], nf1[4], nb0[4], nb1[4];
    unpack(ld4(mf  + i0), mf0); unpack(ld4(mf  + i1), mf1);
    unpack(ld4(lvf + i0), lf0); unpack(ld4(lvf + i1), lf1);
    unpack(ld4(mb  + i0), mb0); unpack(ld4(mb  + i1), mb1);
    unpack(ld4(lvb + i0), lb0); unpack(ld4(lvb + i1), lb1);
    unpack(ld4(tgt + i0), t0);  unpack(ld4(tgt + i1), t1);
    unpack(ld4(nf  + i0), nf0); unpack(ld4(nf  + i1), nf1);
    unpack(ld4(nb  + i0), nb0); unpack(ld4(nb  + i1), nb1);

    float ff0[4], ff1[4], fb0[4], fb1[4];
    float ent = 0.0f, epe = 0.0f;
    #pragma unroll
    for (int i = 0; i < 4; ++i) {
        ff0[i] = mf0[i] + __expf(lf0[i] * 0.5f) * nf0[i];
        ff1[i] = mf1[i] + __expf(lf1[i] * 0.5f) * nf1[i];
        fb0[i] = mb0[i] + __expf(lb0[i] * 0.5f) * nb0[i];
        fb1[i] = mb1[i] + __expf(lb1[i] * 0.5f) * nb1[i];
        ent += lf0[i] + lf1[i] + lb0[i] + lb1[i];
        float d0 = mf0[i] - t0[i], d1 = mf1[i] - t1[i];
        epe += sqrtf(d0 * d0 + d1 * d1);
    }
    st4(&g_flow[0][i0], make_float4(ff0[0], ff0[1], ff0[2], ff0[3]));
    st4(&g_flow[0][i1], make_float4(ff1[0], ff1[1], ff1[2], ff1[3]));
    st4(&g_flow[1][i0], make_float4(fb0[0], fb0[1], fb0[2], fb0[3]));
    st4(&g_flow[1][i1], make_float4(fb1[0], fb1[1], fb1[2], fb1[3]));

    float es = blockReduceSum(ent);
    __syncthreads();
    float ps = blockReduceSum(epe);
    if (threadIdx.x == 0) {
        atomicAdd(&g_acc[1], es);
        atomicAdd(&g_acc[2], ps);
    }
}

// Per-direction main energy (both directions via blockIdx.y), 4 pixels/thread.
__global__ void __launch_bounds__(TPB) k_dir(
    const float* __restrict__ img1, const float* __restrict__ img2)
{
    int dir = blockIdx.y;
    const float* __restrict__ imgA = dir ? img2 : img1;
    const float* __restrict__ imgB = dir ? img1 : img2;

    int q = blockIdx.x * blockDim.x + threadIdx.x;
    int p = q * 4;
    int b  = p / HW;
    int rr = p - b * HW;
    int y  = rr / W;
    int x  = rr - y * W;

    const float* __restrict__ fA = g_flow[dir];
    const float* __restrict__ fB = g_flow[dir ^ 1];
    __half* __restrict__ res  = g_res[dir];
    __half* __restrict__ mout = g_mask[dir];

    int baseF0 = (b * 2) * HW;
    int baseF1 = baseF0 + HW;
    int baseI  = (b * 3) * HW;

    float fax[4], fay[4];
    unpack(ld4(fA + baseF0 + rr), fax);
    unpack(ld4(fA + baseF1 + rr), fay);

    float ia[3][4];
    #pragma unroll
    for (int c = 0; c < 3; ++c) unpack(ld4(imgA + baseI + c * HW + rr), ia[c]);

    const float* fB0 = fB + baseF0;
    const float* fB1 = fB + baseF1;
    const float* ib0 = imgB + baseI;
    const float* ib1 = ib0 + HW;
    const float* ib2 = ib1 + HW;

    float maskv[4], Dv[4], Av[4];
    float rc[3][4];

    #pragma unroll
    for (int i = 0; i < 4; ++i) {
        float Xp = (float)(x + i) + fax[i];
        float Yp = (float)y + fay[i];

        float mx = sigm(Xp + 0.5f) * (1.0f - sigm(Xp - ((float)W - 0.5f)));
        float my = sigm(Yp + 0.5f) * (1.0f - sigm(Yp - ((float)H - 0.5f)));
        float border = mx * my;

        float x0f = floorf(Xp), y0f = floorf(Yp);
        float wx = Xp - x0f,    wy = Yp - y0f;
        int x0 = (int)x0f, y0 = (int)y0f;
        bool vx0 = (x0 >= 0)     && (x0 <= W - 1);
        bool vx1 = (x0 + 1 >= 0) && (x0 + 1 <= W - 1);
        bool vy0 = (y0 >= 0)     && (y0 <= H - 1);
        bool vy1 = (y0 + 1 >= 0) && (y0 + 1 <= H - 1);
        float w00 = (1.0f - wx) * (1.0f - wy) * (float)(vx0 && vy0);
        float w10 = wx * (1.0f - wy)          * (float)(vx1 && vy0);
        float w01 = (1.0f - wx) * wy          * (float)(vx0 && vy1);
        float w11 = wx * wy                    * (float)(vx1 && vy1);
        int cx0 = min(max(x0, 0), W - 1);
        int cx1 = min(max(x0 + 1, 0), W - 1);
        int cy0 = min(max(y0, 0), H - 1);
        int cy1 = min(max(y0 + 1, 0), H - 1);
        int i00 = cy0 * W + cx0;
        int i10 = cy0 * W + cx1;
        int i01 = cy1 * W + cx0;
        int i11 = cy1 * W + cx1;

        float fbw0 = w00 * fB0[i00] + w10 * fB0[i10] + w01 * fB0[i01] + w11 * fB0[i11];
        float fbw1 = w00 * fB1[i00] + w10 * fB1[i10] + w01 * fB1[i01] + w11 * fB1[i11];

        float mag = fax[i] * fax[i] + fay[i] * fay[i] + fbw0 * fbw0 + fbw1 * fbw1;
        float dfx = fax[i] + fbw0;
        float dfy = fay[i] + fbw1;
        float D   = dfx * dfx + dfy * dfy;
        float occ = 1.0f - sigm(D - (0.01f * mag + 0.5f));
        maskv[i] = border * occ;
        Dv[i] = D;

        float w0 = w00 * ib0[i00] + w10 * ib0[i10] + w01 * ib0[i01] + w11 * ib0[i11];
        float w1 = w00 * ib1[i00] + w10 * ib1[i10] + w01 * ib1[i01] + w11 * ib1[i11];
        float w2 = w00 * ib2[i00] + w10 * ib2[i10] + w01 * ib2[i01] + w11 * ib2[i11];
        rc[0][i] = ia[0][i] - w0;
        rc[1][i] = ia[1][i] - w1;
        rc[2][i] = ia[2][i] - w2;
        Av[i] = rc[0][i] * rc[0][i] + rc[1][i] * rc[1][i] + rc[2][i] * rc[2][i];
    }

    // fp16 scratch stores (8B each)
    st_h4(&mout[p], maskv);
    #pragma unroll
    for (int c = 0; c < 3; ++c)
        st_h4(&res[baseI + c * HW + rr], rc[c]);

    // Smoothness
    bool hasR = (x + 4) < W;
    float faxn = hasR ? fA[baseF0 + rr + 4] : 0.0f;
    float fayn = hasR ? fA[baseF1 + rr + 4] : 0.0f;
    bool hasD = (y + 1) < H;
    float faxd[4] = {0, 0, 0, 0}, fayd[4] = {0, 0, 0, 0};
    if (hasD) {
        unpack(ld4(fA + baseF0 + rr + W), faxd);
        unpack(ld4(fA + baseF1 + rr + W), fayd);
    }

    float e = 0.0f;
    #pragma unroll
    for (int i = 0; i < 4; ++i) {
        float dx2 = 0.0f;
        if (x + i < W - 1) {
            float nx = (i < 3) ? fax[i + 1] : faxn;
            float ny = (i < 3) ? fay[i + 1] : fayn;
            float d0 = nx - fax[i];
            float d1 = ny - fay[i];
            dx2 = d0 * d0 + d1 * d1;
        }
        float dy2 = 0.0f;
        if (hasD) {
            float d0 = faxd[i] - fax[i];
            float d1 = fayd[i] - fay[i];
            dy2 = d0 * d0 + d1 * d1;
        }
        e += (1.0f - maskv[i])
           + sqrtf(Av[i] + 1e-5f) * maskv[i]
           + sqrtf(dx2 + dy2 + 1e-5f)
           + sqrtf(Dv[i] + 1e-5f) * maskv[i];
    }

    float bs = blockReduceSum(e);
    if (threadIdx.x == 0) atomicAdd(&g_acc[0], bs);
}

// Gradient-constancy term on fp16 residuals + last-block final output.
__global__ void __launch_bounds__(TPB) k_grad(float* __restrict__ out)
{
    int dir = blockIdx.y;
    int q = blockIdx.x * blockDim.x + threadIdx.x;
    int p = q * 4;
    int b  = p / HW;
    int rr = p - b * HW;
    int y  = rr / W;
    int x  = rr - y * W;

    const __half* __restrict__ res = g_res[dir];
    int baseI = (b * 3) * HW;

    bool hasL = x >= 4;
    bool hasR = (x + 4) < W;
    bool hYm2 = y >= 2, hYm1 = y >= 1, hYp1 = y < H - 1, hYp2 = y < H - 2;

    float Ct[4] = {0, 0, 0, 0};
    #pragma unroll
    for (int c = 0; c < 3; ++c) {
        const __half* rb = res + baseI + c * HW + rr;
        float a[12];
        if (hasL) ld_h4(rb - 4, &a[0]);
        else { a[0] = a[1] = a[2] = a[3] = 0.0f; }
        ld_h4(rb, &a[4]);
        if (hasR) ld_h4(rb + 4, &a[8]);
        else { a[8] = a[9] = a[10] = a[11] = 0.0f; }

        float ym2[4] = {0,0,0,0}, ym1[4] = {0,0,0,0}, yp1[4] = {0,0,0,0}, yp2[4] = {0,0,0,0};
        if (hYm2) ld_h4(rb - 2 * W, ym2);
        if (hYm1) ld_h4(rb - W, ym1);
        if (hYp1) ld_h4(rb + W, yp1);
        if (hYp2) ld_h4(rb + 2 * W, yp2);

        #pragma unroll
        for (int i = 0; i < 4; ++i) {
            float gx = KC0 * a[i + 2] + KC1 * a[i + 3] + KC3 * a[i + 5] + KC4 * a[i + 6];
            float gy = KC0 * ym2[i] + KC1 * ym1[i] + KC3 * yp1[i] + KC4 * yp2[i];
            Ct[i] += gx * gx + gy * gy;
        }
    }

    float m[4];
    ld_h4(&g_mask[dir][p], m);
    float e = 0.0f;
    #pragma unroll
    for (int i = 0; i < 4; ++i) e += sqrtf(Ct[i] + 1e-5f) * m[i];

    float bs = blockReduceSum(e);

    // Last-block epilogue: thread 0 adds partial, fences, counts; the final
    // block computes outputs and resets accumulators for the next replay.
    if (threadIdx.x == 0) {
        atomicAdd(&g_acc[0], bs);
        __threadfence();
        unsigned n = atomicAdd(&g_done, 1u);
        if (n == GRAD_BLOCKS - 1) {
            __threadfence();
            float energy  = g_acc[0] * (1.0f / (float)B);
            float entropy = g_acc[1] * (1.0f / (2.0f * (float)B));
            out[0] = energy - entropy;
            out[1] = g_acc[2] * (1.0f / (float)NPIX);
            g_acc[0] = 0.0f;
            g_acc[1] = 0.0f;
            g_acc[2] = 0.0f;
            g_done = 0u;
        }
    }
}

extern "C" void kernel_launch(void* const* d_in, const int* in_sizes, int n_in,
                              void* d_out, int out_size)
{
    const float* meanf   = (const float*)d_in[0];
    const float* logvarf = (const float*)d_in[1];
    const float* meanb   = (const float*)d_in[2];
    const float* logvarb = (const float*)d_in[3];
    const float* img1    = (const float*)d_in[4];
    const float* img2    = (const float*)d_in[5];
    const float* target  = (const float*)d_in[6];
    const float* noise_f = (const float*)d_in[7];
    const float* noise_b = (const float*)d_in[8];
    float* out = (float*)d_out;

    dim3 grid2(NBLKQ, 2);

    k_flow<<<NBLKQ, TPB>>>(meanf, logvarf, meanb, logvarb, target, noise_f, noise_b);
    k_dir<<<grid2, TPB>>>(img1, img2);
    k_grad<<<grid2, TPB>>>(out);
}

// round 14
// speedup vs baseline: 1.1739x; 1.0327x over previous
#include <cuda_runtime.h>
#include <cuda_fp16.h>
#include <math.h>

// Fixed problem shapes
constexpr int B  = 8;
constexpr int H  = 384;
constexpr int W  = 512;
constexpr int HW = H * W;            // 196608
constexpr int NPIX = B * HW;         // 1572864
constexpr int N2 = B * 2 * HW;
constexpr int N3 = B * 3 * HW;

constexpr int TPB = 256;
constexpr int NQUAD = NPIX / 4;
constexpr int NBLKQ = NQUAD / TPB;          // 1536
constexpr int NOCT  = NPIX / 8;             // 196608 (4x2 tiles)
constexpr int NBLKO = NOCT / TPB;           // 768
constexpr unsigned GRAD_BLOCKS = NBLKO * 2; // 1536

// 5-tap gradient filter coefficients (center tap is 0)
constexpr float KC0 = -1.0f / 12.0f;
constexpr float KC1 =  2.0f / 3.0f;
constexpr float KC3 = -2.0f / 3.0f;
constexpr float KC4 =  1.0f / 12.0f;

// Scratch (static device globals; zero-initialized at module load)
__device__ float  g_flow[2][N2];       // fp32 flow samples
__device__ __half g_res [2][N3];       // fp16 warp residual per direction
__device__ __half g_mask[2][NPIX];     // fp16 border*occ mask per direction
__device__ float  g_acc [3];           // [0]=energy, [1]=logvar raw sum, [2]=epe sum
__device__ unsigned g_done;            // last-block counter

__device__ __forceinline__ float sigm(float x) {
    return 1.0f / (1.0f + __expf(-x));
}
__device__ __forceinline__ float4 ld4(const float* p) {
    return *reinterpret_cast<const float4*>(p);
}
__device__ __forceinline__ void st4(float* p, float4 v) {
    *reinterpret_cast<float4*>(p) = v;
}
__device__ __forceinline__ void unpack(float4 v, float* a) {
    a[0] = v.x; a[1] = v.y; a[2] = v.z; a[3] = v.w;
}
// 4 halfs <-> 4 floats, single 8B transaction
__device__ __forceinline__ void st_h4(__half* p, const float* a) {
    __half2 h0 = __floats2half2_rn(a[0], a[1]);
    __half2 h1 = __floats2half2_rn(a[2], a[3]);
    uint2 u;
    u.x = *reinterpret_cast<unsigned*>(&h0);
    u.y = *reinterpret_cast<unsigned*>(&h1);
    *reinterpret_cast<uint2*>(p) = u;
}
__device__ __forceinline__ void ld_h4(const __half* p, float* a) {
    uint2 u = *reinterpret_cast<const uint2*>(p);
    __half2 h0 = *reinterpret_cast<__half2*>(&u.x);
    __half2 h1 = *reinterpret_cast<__half2*>(&u.y);
    float2 f0 = __half22float2(h0);
    float2 f1 = __half22float2(h1);
    a[0] = f0.x; a[1] = f0.y; a[2] = f1.x; a[3] = f1.y;
}

__device__ __forceinline__ float blockReduceSum(float v) {
    __shared__ float s[32];
    int lane = threadIdx.x & 31;
    int wid  = threadIdx.x >> 5;
    #pragma unroll
    for (int o = 16; o; o >>= 1) v += __shfl_down_sync(0xffffffffu, v, o);
    if (lane == 0) s[wid] = v;
    __syncthreads();
    v = 0.0f;
    if (wid == 0) {
        v = (lane < (TPB >> 5)) ? s[lane] : 0.0f;
        #pragma unroll
        for (int o = 16; o; o >>= 1) v += __shfl_down_sync(0xffffffffu, v, o);
    }
    return v;
}

// Reparameterize flows; two sequential channel phases to keep regs <= 42.
__global__ void __launch_bounds__(TPB, 6) k_flow(
    const float* __restrict__ mf, const float* __restrict__ lvf,
    const float* __restrict__ mb, const float* __restrict__ lvb,
    const float* __restrict__ tgt,
    const float* __restrict__ nf, const float* __restrict__ nb)
{
    int q = blockIdx.x * blockDim.x + threadIdx.x;
    int p = q * 4;
    int b  = p / HW;
    int rr = p - b * HW;
    int i0 = (b * 2) * HW + rr;
    int i1 = i0 + HW;

    float ent = 0.0f, epe = 0.0f;
    float d0sq[4];

    // ---- channel 0 ----
    {
        float a[4], l[4], n[4], t[4], f[4];
        unpack(ld4(mf  + i0), a);
        unpack(ld4(lvf + i0), l);
        unpack(ld4(nf  + i0), n);
        unpack(ld4(tgt + i0), t);
        #pragma unroll
        for (int i = 0; i < 4; ++i) {
            f[i] = a[i] + __expf(l[i] * 0.5f) * n[i];
            ent += l[i];
            float d = a[i] - t[i];
            d0sq[i] = d * d;
        }
        st4(&g_flow[0][i0], make_float4(f[0], f[1], f[2], f[3]));

        unpack(ld4(mb  + i0), a);
        unpack(ld4(lvb + i0), l);
        unpack(ld4(nb  + i0), n);
        #pragma unroll
        for (int i = 0; i < 4; ++i) {
            f[i] = a[i] + __expf(l[i] * 0.5f) * n[i];
            ent += l[i];
        }
        st4(&g_flow[1][i0], make_float4(f[0], f[1], f[2], f[3]));
    }

    // ---- channel 1 ----
    {
        float a[4], l[4], n[4], t[4], f[4];
        unpack(ld4(mf  + i1), a);
        unpack(ld4(lvf + i1), l);
        unpack(ld4(nf  + i1), n);
        unpack(ld4(tgt + i1), t);
        #pragma unroll
        for (int i = 0; i < 4; ++i) {
            f[i] = a[i] + __expf(l[i] * 0.5f) * n[i];
            ent += l[i];
            float d = a[i] - t[i];
            epe += sqrtf(d0sq[i] + d * d);
        }
        st4(&g_flow[0][i1], make_float4(f[0], f[1], f[2], f[3]));

        unpack(ld4(mb  + i1), a);
        unpack(ld4(lvb + i1), l);
        unpack(ld4(nb  + i1), n);
        #pragma unroll
        for (int i = 0; i < 4; ++i) {
            f[i] = a[i] + __expf(l[i] * 0.5f) * n[i];
            ent += l[i];
        }
        st4(&g_flow[1][i1], make_float4(f[0], f[1], f[2], f[3]));
    }

    float es = blockReduceSum(ent);
    __syncthreads();
    float ps = blockReduceSum(epe);
    if (threadIdx.x == 0) {
        atomicAdd(&g_acc[1], es);
        atomicAdd(&g_acc[2], ps);
    }
}

// Per-direction main energy (both directions via blockIdx.y), 4 pixels/thread.
__global__ void __launch_bounds__(TPB) k_dir(
    const float* __restrict__ img1, const float* __restrict__ img2)
{
    int dir = blockIdx.y;
    const float* __restrict__ imgA = dir ? img2 : img1;
    const float* __restrict__ imgB = dir ? img1 : img2;

    int q = blockIdx.x * blockDim.x + threadIdx.x;
    int p = q * 4;
    int b  = p / HW;
    int rr = p - b * HW;
    int y  = rr / W;
    int x  = rr - y * W;

    const float* __restrict__ fA = g_flow[dir];
    const float* __restrict__ fB = g_flow[dir ^ 1];
    __half* __restrict__ res  = g_res[dir];
    __half* __restrict__ mout = g_mask[dir];

    int baseF0 = (b * 2) * HW;
    int baseF1 = baseF0 + HW;
    int baseI  = (b * 3) * HW;

    float fax[4], fay[4];
    unpack(ld4(fA + baseF0 + rr), fax);
    unpack(ld4(fA + baseF1 + rr), fay);

    float ia[3][4];
    #pragma unroll
    for (int c = 0; c < 3; ++c) unpack(ld4(imgA + baseI + c * HW + rr), ia[c]);

    const float* fB0 = fB + baseF0;
    const float* fB1 = fB + baseF1;
    const float* ib0 = imgB + baseI;
    const float* ib1 = ib0 + HW;
    const float* ib2 = ib1 + HW;

    float maskv[4], Dv[4], Av[4];
    float rc[3][4];

    #pragma unroll
    for (int i = 0; i < 4; ++i) {
        float Xp = (float)(x + i) + fax[i];
        float Yp = (float)y + fay[i];

        float mx = sigm(Xp + 0.5f) * (1.0f - sigm(Xp - ((float)W - 0.5f)));
        float my = sigm(Yp + 0.5f) * (1.0f - sigm(Yp - ((float)H - 0.5f)));
        float border = mx * my;

        float x0f = floorf(Xp), y0f = floorf(Yp);
        float wx = Xp - x0f,    wy = Yp - y0f;
        int x0 = (int)x0f, y0 = (int)y0f;
        bool vx0 = (x0 >= 0)     && (x0 <= W - 1);
        bool vx1 = (x0 + 1 >= 0) && (x0 + 1 <= W - 1);
        bool vy0 = (y0 >= 0)     && (y0 <= H - 1);
        bool vy1 = (y0 + 1 >= 0) && (y0 + 1 <= H - 1);
        float w00 = (1.0f - wx) * (1.0f - wy) * (float)(vx0 && vy0);
        float w10 = wx * (1.0f - wy)          * (float)(vx1 && vy0);
        float w01 = (1.0f - wx) * wy          * (float)(vx0 && vy1);
        float w11 = wx * wy                    * (float)(vx1 && vy1);
        int cx0 = min(max(x0, 0), W - 1);
        int cx1 = min(max(x0 + 1, 0), W - 1);
        int cy0 = min(max(y0, 0), H - 1);
        int cy1 = min(max(y0 + 1, 0), H - 1);
        int i00 = cy0 * W + cx0;
        int i10 = cy0 * W + cx1;
        int i01 = cy1 * W + cx0;
        int i11 = cy1 * W + cx1;

        float fbw0 = w00 * fB0[i00] + w10 * fB0[i10] + w01 * fB0[i01] + w11 * fB0[i11];
        float fbw1 = w00 * fB1[i00] + w10 * fB1[i10] + w01 * fB1[i01] + w11 * fB1[i11];

        float mag = fax[i] * fax[i] + fay[i] * fay[i] + fbw0 * fbw0 + fbw1 * fbw1;
        float dfx = fax[i] + fbw0;
        float dfy = fay[i] + fbw1;
        float D   = dfx * dfx + dfy * dfy;
        float occ = 1.0f - sigm(D - (0.01f * mag + 0.5f));
        maskv[i] = border * occ;
        Dv[i] = D;

        float w0 = w00 * ib0[i00] + w10 * ib0[i10] + w01 * ib0[i01] + w11 * ib0[i11];
        float w1 = w00 * ib1[i00] + w10 * ib1[i10] + w01 * ib1[i01] + w11 * ib1[i11];
        float w2 = w00 * ib2[i00] + w10 * ib2[i10] + w01 * ib2[i01] + w11 * ib2[i11];
        rc[0][i] = ia[0][i] - w0;
        rc[1][i] = ia[1][i] - w1;
        rc[2][i] = ia[2][i] - w2;
        Av[i] = rc[0][i] * rc[0][i] + rc[1][i] * rc[1][i] + rc[2][i] * rc[2][i];
    }

    st_h4(&mout[p], maskv);
    #pragma unroll
    for (int c = 0; c < 3; ++c)
        st_h4(&res[baseI + c * HW + rr], rc[c]);

    // Smoothness
    bool hasR = (x + 4) < W;
    float faxn = hasR ? fA[baseF0 + rr + 4] : 0.0f;
    float fayn = hasR ? fA[baseF1 + rr + 4] : 0.0f;
    bool hasD = (y + 1) < H;
    float faxd[4] = {0, 0, 0, 0}, fayd[4] = {0, 0, 0, 0};
    if (hasD) {
        unpack(ld4(fA + baseF0 + rr + W), faxd);
        unpack(ld4(fA + baseF1 + rr + W), fayd);
    }

    float e = 0.0f;
    #pragma unroll
    for (int i = 0; i < 4; ++i) {
        float dx2 = 0.0f;
        if (x + i < W - 1) {
            float nx = (i < 3) ? fax[i + 1] : faxn;
            float ny = (i < 3) ? fay[i + 1] : fayn;
            float d0 = nx - fax[i];
            float d1 = ny - fay[i];
            dx2 = d0 * d0 + d1 * d1;
        }
        float dy2 = 0.0f;
        if (hasD) {
            float d0 = faxd[i] - fax[i];
            float d1 = fayd[i] - fay[i];
            dy2 = d0 * d0 + d1 * d1;
        }
        e += (1.0f - maskv[i])
           + sqrtf(Av[i] + 1e-5f) * maskv[i]
           + sqrtf(dx2 + dy2 + 1e-5f)
           + sqrtf(Dv[i] + 1e-5f) * maskv[i];
    }

    float bs = blockReduceSum(e);
    if (threadIdx.x == 0) atomicAdd(&g_acc[0], bs);
}

// Gradient-constancy term on fp16 residuals, 4x2-pixel tile per thread,
// plus last-block final output.
__global__ void __launch_bounds__(TPB) k_grad(float* __restrict__ out)
{
    int dir = blockIdx.y;
    int qid = blockIdx.x * blockDim.x + threadIdx.x;   // [0, NOCT)
    int qx = qid & 127;                  // 128 quads per row
    int rp = qid >> 7;                   // row-pair index
    int b  = rp / (H / 2);
    int y  = 2 * (rp - b * (H / 2));     // even row in [0, H-2]
    int x  = qx * 4;
    int rr = y * W + x;

    const __half* __restrict__ res = g_res[dir];
    int baseI = (b * 3) * HW;

    bool hasL = x >= 4;
    bool hasR = (x + 4) < W;
    bool hYm2 = y >= 2, hYm1 = y >= 1;
    bool hYp2 = (y + 2) < H, hYp3 = (y + 3) < H;

    float Ct0[4] = {0, 0, 0, 0};
    float Ct1[4] = {0, 0, 0, 0};

    #pragma unroll
    for (int c = 0; c < 3; ++c) {
        const __half* rb = res + baseI + c * HW + rr;

        // Horizontal rows (with +-4 halo): rows y and y+1
        float a0[12], a1[12];
        if (hasL) { ld_h4(rb - 4, &a0[0]); ld_h4(rb + W - 4, &a1[0]); }
        else { a0[0]=a0[1]=a0[2]=a0[3]=0.0f; a1[0]=a1[1]=a1[2]=a1[3]=0.0f; }
        ld_h4(rb,     &a0[4]);
        ld_h4(rb + W, &a1[4]);
        if (hasR) { ld_h4(rb + 4, &a0[8]); ld_h4(rb + W + 4, &a1[8]); }
        else { a0[8]=a0[9]=a0[10]=a0[11]=0.0f; a1[8]=a1[9]=a1[10]=a1[11]=0.0f; }

        // Vertical extra rows: y-2, y-1, y+2, y+3
        float rm2[4] = {0,0,0,0}, rm1[4] = {0,0,0,0}, rp2[4] = {0,0,0,0}, rp3[4] = {0,0,0,0};
        if (hYm2) ld_h4(rb - 2 * W, rm2);
        if (hYm1) ld_h4(rb - W, rm1);
        if (hYp2) ld_h4(rb + 2 * W, rp2);
        if (hYp3) ld_h4(rb + 3 * W, rp3);

        #pragma unroll
        for (int i = 0; i < 4; ++i) {
            // Row y
            float gx0 = KC0 * a0[i + 2] + KC1 * a0[i + 3] + KC3 * a0[i + 5] + KC4 * a0[i + 6];
            float gy0 = KC0 * rm2[i] + KC1 * rm1[i] + KC3 * a1[i + 4] + KC4 * rp2[i];
            Ct0[i] += gx0 * gx0 + gy0 * gy0;
            // Row y+1
            float gx1 = KC0 * a1[i + 2] + KC1 * a1[i + 3] + KC3 * a1[i + 5] + KC4 * a1[i + 6];
            float gy1 = KC0 * rm1[i] + KC1 * a0[i + 4] + KC3 * rp2[i] + KC4 * rp3[i];
            Ct1[i] += gx1 * gx1 + gy1 * gy1;
        }
    }

    int pm = b * HW + rr;
    float m0[4], m1[4];
    ld_h4(&g_mask[dir][pm], m0);
    ld_h4(&g_mask[dir][pm + W], m1);

    float e = 0.0f;
    #pragma unroll
    for (int i = 0; i < 4; ++i) {
        e += sqrtf(Ct0[i] + 1e-5f) * m0[i];
        e += sqrtf(Ct1[i] + 1e-5f) * m1[i];
    }

    float bs = blockReduceSum(e);

    // Last-block epilogue
    if (threadIdx.x == 0) {
        atomicAdd(&g_acc[0], bs);
        __threadfence();
        unsigned n = atomicAdd(&g_done, 1u);
        if (n == GRAD_BLOCKS - 1) {
            __threadfence();
            float energy  = g_acc[0] * (1.0f / (float)B);
            float entropy = g_acc[1] * (1.0f / (2.0f * (float)B));
            out[0] = energy - entropy;
            out[1] = g_acc[2] * (1.0f / (float)NPIX);
            g_acc[0] = 0.0f;
            g_acc[1] = 0.0f;
            g_acc[2] = 0.0f;
            g_done = 0u;
        }
    }
}

extern "C" void kernel_launch(void* const* d_in, const int* in_sizes, int n_in,
                              void* d_out, int out_size)
{
    const float* meanf   = (const float*)d_in[0];
    const float* logvarf = (const float*)d_in[1];
    const float* meanb   = (const float*)d_in[2];
    const float* logvarb = (const float*)d_in[3];
    const float* img1    = (const float*)d_in[4];
    const float* img2    = (const float*)d_in[5];
    const float* target  = (const float*)d_in[6];
    const float* noise_f = (const float*)d_in[7];
    const float* noise_b = (const float*)d_in[8];
    float* out = (float*)d_out;

    dim3 gridD(NBLKQ, 2);
    dim3 gridG(NBLKO, 2);

    k_flow<<<NBLKQ, TPB>>>(meanf, logvarf, meanb, logvarb, target, noise_f, noise_b);
    k_dir<<<gridD, TPB>>>(img1, img2);
    k_grad<<<gridG, TPB>>>(out);
}

// round 15
// speedup vs baseline: 1.3634x; 1.1615x over previous
#include <cuda_runtime.h>
#include <cuda_fp16.h>
#include <math.h>

// Fixed problem shapes
constexpr int B  = 8;
constexpr int H  = 384;
constexpr int W  = 512;
constexpr int HW = H * W;            // 196608
constexpr int NPIX = B * HW;         // 1572864
constexpr int N3 = B * 3 * HW;

constexpr int TPB = 256;
constexpr int NQUAD = NPIX / 4;
constexpr int NBLKQ = NQUAD / TPB;          // 1536
constexpr int NOCT  = NPIX / 8;             // 196608 (4x2 tiles)
constexpr int NBLKO = NOCT / TPB;           // 768
constexpr unsigned GRAD_BLOCKS = NBLKO * 2; // 1536

// 5-tap gradient filter coefficients (center tap is 0)
constexpr float KC0 = -1.0f / 12.0f;
constexpr float KC1 =  2.0f / 3.0f;
constexpr float KC3 = -2.0f / 3.0f;
constexpr float KC4 =  1.0f / 12.0f;

// Scratch (static device globals; zero-initialized at module load)
__device__ __half2 g_flow[2][NPIX];    // interleaved (fx,fy) fp16 per pixel
__device__ __half  g_res [2][N3];      // fp16 warp residual per direction
__device__ __half  g_mask[2][NPIX];    // fp16 border*occ mask per direction
__device__ float   g_acc [3];          // [0]=energy, [1]=logvar raw, [2]=epe
__device__ unsigned g_done;            // last-block counter

__device__ __forceinline__ float sigm(float x) {
    return 1.0f / (1.0f + __expf(-x));
}
__device__ __forceinline__ float4 ld4(const float* p) {
    return *reinterpret_cast<const float4*>(p);
}
__device__ __forceinline__ void unpack(float4 v, float* a) {
    a[0] = v.x; a[1] = v.y; a[2] = v.z; a[3] = v.w;
}
// 4 halfs <-> 4 floats, single 8B transaction
__device__ __forceinline__ void st_h4(__half* p, const float* a) {
    __half2 h0 = __floats2half2_rn(a[0], a[1]);
    __half2 h1 = __floats2half2_rn(a[2], a[3]);
    uint2 u;
    u.x = *reinterpret_cast<unsigned*>(&h0);
    u.y = *reinterpret_cast<unsigned*>(&h1);
    *reinterpret_cast<uint2*>(p) = u;
}
__device__ __forceinline__ void ld_h4(const __half* p, float* a) {
    uint2 u = *reinterpret_cast<const uint2*>(p);
    __half2 h0 = *reinterpret_cast<__half2*>(&u.x);
    __half2 h1 = *reinterpret_cast<__half2*>(&u.y);
    float2 f0 = __half22float2(h0);
    float2 f1 = __half22float2(h1);
    a[0] = f0.x; a[1] = f0.y; a[2] = f1.x; a[3] = f1.y;
}
// Load 4 interleaved flow pixels (16B) into fx[4], fy[4]
__device__ __forceinline__ void ld_flow4(const __half2* p, float* fx, float* fy) {
    uint4 u = *reinterpret_cast<const uint4*>(p);
    const __half2* h = reinterpret_cast<const __half2*>(&u);
    #pragma unroll
    for (int i = 0; i < 4; ++i) {
        float2 f = __half22float2(h[i]);
        fx[i] = f.x; fy[i] = f.y;
    }
}

__device__ __forceinline__ float blockReduceSum(float v) {
    __shared__ float s[32];
    int lane = threadIdx.x & 31;
    int wid  = threadIdx.x >> 5;
    #pragma unroll
    for (int o = 16; o; o >>= 1) v += __shfl_down_sync(0xffffffffu, v, o);
    if (lane == 0) s[wid] = v;
    __syncthreads();
    v = 0.0f;
    if (wid == 0) {
        v = (lane < (TPB >> 5)) ? s[lane] : 0.0f;
        #pragma unroll
        for (int o = 16; o; o >>= 1) v += __shfl_down_sync(0xffffffffu, v, o);
    }
    return v;
}

// Reparameterize flows into interleaved fp16x2; entropy raw-sum + EPE sum.
__global__ void __launch_bounds__(TPB, 6) k_flow(
    const float* __restrict__ mf, const float* __restrict__ lvf,
    const float* __restrict__ mb, const float* __restrict__ lvb,
    const float* __restrict__ tgt,
    const float* __restrict__ nf, const float* __restrict__ nb)
{
    int q = blockIdx.x * blockDim.x + threadIdx.x;
    int p = q * 4;
    int b  = p / HW;
    int rr = p - b * HW;
    int i0 = (b * 2) * HW + rr;
    int i1 = i0 + HW;

    float ent = 0.0f, epe = 0.0f;

    // ---- forward flow ----
    {
        float f0[4], f1[4], d0sq[4];
        {
            float a[4], l[4], n[4], t[4];
            unpack(ld4(mf  + i0), a);
            unpack(ld4(lvf + i0), l);
            unpack(ld4(nf  + i0), n);
            unpack(ld4(tgt + i0), t);
            #pragma unroll
            for (int i = 0; i < 4; ++i) {
                f0[i] = a[i] + __expf(l[i] * 0.5f) * n[i];
                ent += l[i];
                float d = a[i] - t[i];
                d0sq[i] = d * d;
            }
        }
        {
            float a[4], l[4], n[4], t[4];
            unpack(ld4(mf  + i1), a);
            unpack(ld4(lvf + i1), l);
            unpack(ld4(nf  + i1), n);
            unpack(ld4(tgt + i1), t);
            #pragma unroll
            for (int i = 0; i < 4; ++i) {
                f1[i] = a[i] + __expf(l[i] * 0.5f) * n[i];
                ent += l[i];
                float d = a[i] - t[i];
                epe += sqrtf(d0sq[i] + d * d);
            }
        }
        __half2 h[4];
        #pragma unroll
        for (int i = 0; i < 4; ++i) h[i] = __floats2half2_rn(f0[i], f1[i]);
        *reinterpret_cast<uint4*>(&g_flow[0][b * HW + rr]) =
            *reinterpret_cast<uint4*>(h);
    }

    // ---- backward flow ----
    {
        float f0[4], f1[4];
        {
            float a[4], l[4], n[4];
            unpack(ld4(mb  + i0), a);
            unpack(ld4(lvb + i0), l);
            unpack(ld4(nb  + i0), n);
            #pragma unroll
            for (int i = 0; i < 4; ++i) {
                f0[i] = a[i] + __expf(l[i] * 0.5f) * n[i];
                ent += l[i];
            }
        }
        {
            float a[4], l[4], n[4];
            unpack(ld4(mb  + i1), a);
            unpack(ld4(lvb + i1), l);
            unpack(ld4(nb  + i1), n);
            #pragma unroll
            for (int i = 0; i < 4; ++i) {
                f1[i] = a[i] + __expf(l[i] * 0.5f) * n[i];
                ent += l[i];
            }
        }
        __half2 h[4];
        #pragma unroll
        for (int i = 0; i < 4; ++i) h[i] = __floats2half2_rn(f0[i], f1[i]);
        *reinterpret_cast<uint4*>(&g_flow[1][b * HW + rr]) =
            *reinterpret_cast<uint4*>(h);
    }

    float es = blockReduceSum(ent);
    __syncthreads();
    float ps = blockReduceSum(epe);
    if (threadIdx.x == 0) {
        atomicAdd(&g_acc[1], es);
        atomicAdd(&g_acc[2], ps);
    }
}

// Per-direction main energy (both directions via blockIdx.y), 4 pixels/thread.
__global__ void __launch_bounds__(TPB) k_dir(
    const float* __restrict__ img1, const float* __restrict__ img2)
{
    int dir = blockIdx.y;
    const float* __restrict__ imgA = dir ? img2 : img1;
    const float* __restrict__ imgB = dir ? img1 : img2;

    int q = blockIdx.x * blockDim.x + threadIdx.x;
    int p = q * 4;
    int b  = p / HW;
    int rr = p - b * HW;
    int y  = rr / W;
    int x  = rr - y * W;

    const __half2* __restrict__ fA = g_flow[dir]     + b * HW;
    const __half2* __restrict__ fB = g_flow[dir ^ 1] + b * HW;
    __half* __restrict__ res  = g_res[dir];
    __half* __restrict__ mout = g_mask[dir];

    int baseI = (b * 3) * HW;

    float fax[4], fay[4];
    ld_flow4(fA + rr, fax, fay);

    float ia[3][4];
    #pragma unroll
    for (int c = 0; c < 3; ++c) unpack(ld4(imgA + baseI + c * HW + rr), ia[c]);

    const float* ib0 = imgB + baseI;
    const float* ib1 = ib0 + HW;
    const float* ib2 = ib1 + HW;

    float maskv[4], Dv[4], Av[4];
    float rc[3][4];

    #pragma unroll
    for (int i = 0; i < 4; ++i) {
        float Xp = (float)(x + i) + fax[i];
        float Yp = (float)y + fay[i];

        float mx = sigm(Xp + 0.5f) * (1.0f - sigm(Xp - ((float)W - 0.5f)));
        float my = sigm(Yp + 0.5f) * (1.0f - sigm(Yp - ((float)H - 0.5f)));
        float border = mx * my;

        float x0f = floorf(Xp), y0f = floorf(Yp);
        float wx = Xp - x0f,    wy = Yp - y0f;
        int x0 = (int)x0f, y0 = (int)y0f;
        bool vx0 = (x0 >= 0)     && (x0 <= W - 1);
        bool vx1 = (x0 + 1 >= 0) && (x0 + 1 <= W - 1);
        bool vy0 = (y0 >= 0)     && (y0 <= H - 1);
        bool vy1 = (y0 + 1 >= 0) && (y0 + 1 <= H - 1);
        float w00 = (1.0f - wx) * (1.0f - wy) * (float)(vx0 && vy0);
        float w10 = wx * (1.0f - wy)          * (float)(vx1 && vy0);
        float w01 = (1.0f - wx) * wy          * (float)(vx0 && vy1);
        float w11 = wx * wy                    * (float)(vx1 && vy1);
        int cx0 = min(max(x0, 0), W - 1);
        int cx1 = min(max(x0 + 1, 0), W - 1);
        int cy0 = min(max(y0, 0), H - 1);
        int cy1 = min(max(y0 + 1, 0), H - 1);
        int i00 = cy0 * W + cx0;
        int i10 = cy0 * W + cx1;
        int i01 = cy1 * W + cx0;
        int i11 = cy1 * W + cx1;

        // Interleaved fp16x2 flow gather: 4 loads give both channels
        float2 f00 = __half22float2(fB[i00]);
        float2 f10 = __half22float2(fB[i10]);
        float2 f01 = __half22float2(fB[i01]);
        float2 f11 = __half22float2(fB[i11]);
        float fbw0 = w00 * f00.x + w10 * f10.x + w01 * f01.x + w11 * f11.x;
        float fbw1 = w00 * f00.y + w10 * f10.y + w01 * f01.y + w11 * f11.y;

        float mag = fax[i] * fax[i] + fay[i] * fay[i] + fbw0 * fbw0 + fbw1 * fbw1;
        float dfx = fax[i] + fbw0;
        float dfy = fay[i] + fbw1;
        float D   = dfx * dfx + dfy * dfy;
        float occ = 1.0f - sigm(D - (0.01f * mag + 0.5f));
        maskv[i] = border * occ;
        Dv[i] = D;

        float w0 = w00 * ib0[i00] + w10 * ib0[i10] + w01 * ib0[i01] + w11 * ib0[i11];
        float w1 = w00 * ib1[i00] + w10 * ib1[i10] + w01 * ib1[i01] + w11 * ib1[i11];
        float w2 = w00 * ib2[i00] + w10 * ib2[i10] + w01 * ib2[i01] + w11 * ib2[i11];
        rc[0][i] = ia[0][i] - w0;
        rc[1][i] = ia[1][i] - w1;
        rc[2][i] = ia[2][i] - w2;
        Av[i] = rc[0][i] * rc[0][i] + rc[1][i] * rc[1][i] + rc[2][i] * rc[2][i];
    }

    st_h4(&mout[p], maskv);
    #pragma unroll
    for (int c = 0; c < 3; ++c)
        st_h4(&res[baseI + c * HW + rr], rc[c]);

    // Smoothness
    bool hasR = (x + 4) < W;
    float faxn = 0.0f, fayn = 0.0f;
    if (hasR) {
        float2 fn = __half22float2(fA[rr + 4]);
        faxn = fn.x; fayn = fn.y;
    }
    bool hasD = (y + 1) < H;
    float faxd[4] = {0, 0, 0, 0}, fayd[4] = {0, 0, 0, 0};
    if (hasD) ld_flow4(fA + rr + W, faxd, fayd);

    float e = 0.0f;
    #pragma unroll
    for (int i = 0; i < 4; ++i) {
        float dx2 = 0.0f;
        if (x + i < W - 1) {
            float nx = (i < 3) ? fax[i + 1] : faxn;
            float ny = (i < 3) ? fay[i + 1] : fayn;
            float d0 = nx - fax[i];
            float d1 = ny - fay[i];
            dx2 = d0 * d0 + d1 * d1;
        }
        float dy2 = 0.0f;
        if (hasD) {
            float d0 = faxd[i] - fax[i];
            float d1 = fayd[i] - fay[i];
            dy2 = d0 * d0 + d1 * d1;
        }
        e += (1.0f - maskv[i])
           + sqrtf(Av[i] + 1e-5f) * maskv[i]
           + sqrtf(dx2 + dy2 + 1e-5f)
           + sqrtf(Dv[i] + 1e-5f) * maskv[i];
    }

    float bs = blockReduceSum(e);
    if (threadIdx.x == 0) atomicAdd(&g_acc[0], bs);
}

// Gradient-constancy term on fp16 residuals, 4x2-pixel tile per thread,
// plus last-block final output.
__global__ void __launch_bounds__(TPB) k_grad(float* __restrict__ out)
{
    int dir = blockIdx.y;
    int qid = blockIdx.x * blockDim.x + threadIdx.x;   // [0, NOCT)
    int qx = qid & 127;                  // 128 quads per row
    int rp = qid >> 7;                   // row-pair index
    int b  = rp / (H / 2);
    int y  = 2 * (rp - b * (H / 2));     // even row in [0, H-2]
    int x  = qx * 4;
    int rr = y * W + x;

    const __half* __restrict__ res = g_res[dir];
    int baseI = (b * 3) * HW;

    bool hasL = x >= 4;
    bool hasR = (x + 4) < W;
    bool hYm2 = y >= 2, hYm1 = y >= 1;
    bool hYp2 = (y + 2) < H, hYp3 = (y + 3) < H;

    float Ct0[4] = {0, 0, 0, 0};
    float Ct1[4] = {0, 0, 0, 0};

    #pragma unroll
    for (int c = 0; c < 3; ++c) {
        const __half* rb = res + baseI + c * HW + rr;

        float a0[12], a1[12];
        if (hasL) { ld_h4(rb - 4, &a0[0]); ld_h4(rb + W - 4, &a1[0]); }
        else { a0[0]=a0[1]=a0[2]=a0[3]=0.0f; a1[0]=a1[1]=a1[2]=a1[3]=0.0f; }
        ld_h4(rb,     &a0[4]);
        ld_h4(rb + W, &a1[4]);
        if (hasR) { ld_h4(rb + 4, &a0[8]); ld_h4(rb + W + 4, &a1[8]); }
        else { a0[8]=a0[9]=a0[10]=a0[11]=0.0f; a1[8]=a1[9]=a1[10]=a1[11]=0.0f; }

        float rm2[4] = {0,0,0,0}, rm1[4] = {0,0,0,0}, rp2[4] = {0,0,0,0}, rp3[4] = {0,0,0,0};
        if (hYm2) ld_h4(rb - 2 * W, rm2);
        if (hYm1) ld_h4(rb - W, rm1);
        if (hYp2) ld_h4(rb + 2 * W, rp2);
        if (hYp3) ld_h4(rb + 3 * W, rp3);

        #pragma unroll
        for (int i = 0; i < 4; ++i) {
            float gx0 = KC0 * a0[i + 2] + KC1 * a0[i + 3] + KC3 * a0[i + 5] + KC4 * a0[i + 6];
            float gy0 = KC0 * rm2[i] + KC1 * rm1[i] + KC3 * a1[i + 4] + KC4 * rp2[i];
            Ct0[i] += gx0 * gx0 + gy0 * gy0;
            float gx1 = KC0 * a1[i + 2] + KC1 * a1[i + 3] + KC3 * a1[i + 5] + KC4 * a1[i + 6];
            float gy1 = KC0 * rm1[i] + KC1 * a0[i + 4] + KC3 * rp2[i] + KC4 * rp3[i];
            Ct1[i] += gx1 * gx1 + gy1 * gy1;
        }
    }

    int pm = b * HW + rr;
    float m0[4], m1[4];
    ld_h4(&g_mask[dir][pm], m0);
    ld_h4(&g_mask[dir][pm + W], m1);

    float e = 0.0f;
    #pragma unroll
    for (int i = 0; i < 4; ++i) {
        e += sqrtf(Ct0[i] + 1e-5f) * m0[i];
        e += sqrtf(Ct1[i] + 1e-5f) * m1[i];
    }

    float bs = blockReduceSum(e);

    // Last-block epilogue
    if (threadIdx.x == 0) {
        atomicAdd(&g_acc[0], bs);
        __threadfence();
        unsigned n = atomicAdd(&g_done, 1u);
        if (n == GRAD_BLOCKS - 1) {
            __threadfence();
            float energy  = g_acc[0] * (1.0f / (float)B);
            float entropy = g_acc[1] * (1.0f / (2.0f * (float)B));
            out[0] = energy - entropy;
            out[1] = g_acc[2] * (1.0f / (float)NPIX);
            g_acc[0] = 0.0f;
            g_acc[1] = 0.0f;
            g_acc[2] = 0.0f;
            g_done = 0u;
        }
    }
}

extern "C" void kernel_launch(void* const* d_in, const int* in_sizes, int n_in,
                              void* d_out, int out_size)
{
    const float* meanf   = (const float*)d_in[0];
    const float* logvarf = (const float*)d_in[1];
    const float* meanb   = (const float*)d_in[2];
    const float* logvarb = (const float*)d_in[3];
    const float* img1    = (const float*)d_in[4];
    const float* img2    = (const float*)d_in[5];
    const float* target  = (const float*)d_in[6];
    const float* noise_f = (const float*)d_in[7];
    const float* noise_b = (const float*)d_in[8];
    float* out = (float*)d_out;

    dim3 gridD(NBLKQ, 2);
    dim3 gridG(NBLKO, 2);

    k_flow<<<NBLKQ, TPB>>>(meanf, logvarf, meanb, logvarb, target, noise_f, noise_b);
    k_dir<<<gridD, TPB>>>(img1, img2);
    k_grad<<<gridG, TPB>>>(out);
}